// round 6
// baseline (speedup 1.0000x reference)
#include <cuda_runtime.h>
#include <cstdint>

#define N_NODES 100000
#define N_EDGES 3200000
#define F_IN    512
#define HID     16
#define N_CLASSES 40
#define CAP     128   // per-node in-edge bucket capacity (deg~Poisson(32): P(>127)~0)

#define B_FILL  3125  // N_EDGES/4/256
#define B_GEMM  391   // ceil(N_NODES/256)
#define B_MAIN  3516  // interleaved: vb%9==0 -> gemm, else fill

// Scratch (device globals: allocation-free)
__device__ float g_hg[N_NODES * HID];      // hg = relu(x@W1^T+b1) @ Wg^T
__device__ float g_hs[N_NODES * HID];      // hs = hg * dinv
__device__ int   g_cnt[N_NODES];           // in-degree counter / slot allocator
__device__ int   g_slots[N_NODES * CAP];   // bucketed CSR: src ids per dst
__device__ float g_out[N_NODES * HID];     // aggregated messages
__device__ int   g_is64;

// ---------- packed f32x2 helpers (Blackwell) ----------
__device__ __forceinline__ unsigned long long pack2(float x, float y) {
    unsigned long long r;
    asm("mov.b64 %0, {%1,%2};" : "=l"(r) : "f"(x), "f"(y));
    return r;
}
__device__ __forceinline__ void unpack2(unsigned long long v, float& x, float& y) {
    asm("mov.b64 {%0,%1}, %2;" : "=f"(x), "=f"(y) : "l"(v));
}
__device__ __forceinline__ void fma2(unsigned long long& a, unsigned long long b, unsigned long long c) {
    asm("fma.rn.f32x2 %0, %1, %2, %0;" : "+l"(a) : "l"(b), "l"(c));
}

// ---------- prep: zero counters + dtype detect (int64 vs int32 edge_index) ----------
// Detect: 64 int64 samples, stride N_EDGES/64 -> max byte offset 25.2MB, always
// in-bounds (int32 buffer = 25.6MB). int32 data read as int64 -> OOR w.h.p.
__global__ __launch_bounds__(256) void k_prep(const void* e) {
    int i = blockIdx.x * 256 + threadIdx.x;
    if (i < N_NODES) g_cnt[i] = 0;
    if (blockIdx.x == 0 && threadIdx.x < 64) {
        int t = threadIdx.x;
        const long long* p = (const long long*)e;
        long long v = p[(long long)t * (N_EDGES / 64)];
        int ok = (v >= 0 && v < N_NODES) ? 1 : 0;
        unsigned m = __ballot_sync(0xFFFFFFFFu, ok);
        __shared__ unsigned sm[2];
        if ((t & 31) == 0) sm[t >> 5] = m;
        __syncthreads();
        if (t == 0) g_is64 = (sm[0] == 0xFFFFFFFFu && sm[1] == 0xFFFFFFFFu) ? 1 : 0;
    }
}

// ---------- fused main: gemm blocks (vb%9==0) + CSR-fill blocks (else) ----------
__global__ __launch_bounds__(256) void k_main(
    const float4* __restrict__ x4,
    const float* __restrict__ W1,
    const float* __restrict__ b1,
    const float* __restrict__ Wg,
    const void* __restrict__ e)
{
    __shared__ ulonglong2 ws[256][8];   // packed W1 pairs (gemm blocks only)
    __shared__ float sWg[HID * HID];
    __shared__ float sb1[HID];

    int vb = blockIdx.x;
    int tid = threadIdx.x;

    if (vb % 9 != 0) {
        // ---- fill branch: 4 edges/thread, batched atomics then stores ----
        int fill_id = vb - vb / 9 - 1;
        if (fill_id >= B_FILL) return;
        int t = fill_id * 256 + tid;
        if (t >= N_EDGES / 4) return;
        int s[4], d[4];
        if (g_is64) {
            const longlong4* ps = (const longlong4*)e;
            const longlong4* pd = (const longlong4*)((const long long*)e + N_EDGES);
            longlong4 a = ps[t];
            longlong4 b = pd[t];
            s[0] = (int)a.x; s[1] = (int)a.y; s[2] = (int)a.z; s[3] = (int)a.w;
            d[0] = (int)b.x; d[1] = (int)b.y; d[2] = (int)b.z; d[3] = (int)b.w;
        } else {
            const int4* ps = (const int4*)e;
            const int4* pd = (const int4*)((const int*)e + N_EDGES);
            int4 a = ps[t];
            int4 b = pd[t];
            s[0] = a.x; s[1] = a.y; s[2] = a.z; s[3] = a.w;
            d[0] = b.x; d[1] = b.y; d[2] = b.z; d[3] = b.w;
        }
        int pos[4];
        #pragma unroll
        for (int k = 0; k < 4; k++) pos[k] = atomicAdd(&g_cnt[d[k]], 1);
        #pragma unroll
        for (int k = 0; k < 4; k++)
            if (pos[k] < CAP) g_slots[d[k] * CAP + pos[k]] = s[k];
        return;
    }

    // ---- gemm branch: hg = (relu(x @ W1^T + b1)) @ Wg^T ----
    int gemm_id = vb / 9;
    if (gemm_id >= B_GEMM) return;

    for (int idx = tid; idx < 256 * 8; idx += 256) {
        int kp = idx >> 3, jp = idx & 7;
        int j0 = jp * 2;
        ulonglong2 v;
        v.x = pack2(W1[j0 * F_IN + 2 * kp],       W1[j0 * F_IN + 2 * kp + 1]);
        v.y = pack2(W1[(j0 + 1) * F_IN + 2 * kp], W1[(j0 + 1) * F_IN + 2 * kp + 1]);
        ws[kp][jp] = v;
    }
    for (int idx = tid; idx < HID * HID; idx += 256) sWg[idx] = Wg[idx];
    for (int idx = tid; idx < HID; idx += 256)       sb1[idx] = b1[idx];
    __syncthreads();

    int node = gemm_id * 256 + tid;
    if (node >= N_NODES) return;

    unsigned long long acc[16];
    #pragma unroll
    for (int j = 0; j < 16; j++) acc[j] = 0ull;

    const float4* xr = x4 + (long long)node * (F_IN / 4);
    #pragma unroll 4
    for (int q = 0; q < F_IN / 4; q++) {
        float4 xv = __ldg(xr + q);
        unsigned long long xa = pack2(xv.x, xv.y);
        unsigned long long xb = pack2(xv.z, xv.w);
        #pragma unroll
        for (int jp = 0; jp < 8; jp++) {
            ulonglong2 w = ws[2 * q][jp];
            fma2(acc[2 * jp],     xa, w.x);
            fma2(acc[2 * jp + 1], xa, w.y);
        }
        #pragma unroll
        for (int jp = 0; jp < 8; jp++) {
            ulonglong2 w = ws[2 * q + 1][jp];
            fma2(acc[2 * jp],     xb, w.x);
            fma2(acc[2 * jp + 1], xb, w.y);
        }
    }

    float h1[HID];
    #pragma unroll
    for (int j = 0; j < HID; j++) {
        float lo, hi;
        unpack2(acc[j], lo, hi);
        float v = lo + hi + sb1[j];
        h1[j] = v > 0.f ? v : 0.f;
    }

    float* hgp = g_hg + (long long)node * HID;
    #pragma unroll
    for (int j2 = 0; j2 < HID; j2 += 4) {
        float s0 = 0.f, s1 = 0.f, s2 = 0.f, s3 = 0.f;
        #pragma unroll
        for (int j = 0; j < HID; j++) {
            float hv = h1[j];
            s0 += hv * sWg[(j2 + 0) * HID + j];
            s1 += hv * sWg[(j2 + 1) * HID + j];
            s2 += hv * sWg[(j2 + 2) * HID + j];
            s3 += hv * sWg[(j2 + 3) * HID + j];
        }
        *(float4*)(hgp + j2) = make_float4(s0, s1, s2, s3);
    }
}

// ---------- hs = hg * rsqrt(deg) ----------
__global__ __launch_bounds__(256) void k_dinv() {
    int i = blockIdx.x * 256 + threadIdx.x;
    if (i >= N_NODES) return;
    float dv = rsqrtf((float)(g_cnt[i] + 1));   // +1 self loop
    const float4* h = (const float4*)(g_hg + (long long)i * HID);
    float4* o = (float4*)(g_hs + (long long)i * HID);
    #pragma unroll
    for (int q = 0; q < 4; q++) {
        float4 v = h[q];
        v.x *= dv; v.y *= dv; v.z *= dv; v.w *= dv;
        o[q] = v;
    }
}

// ---------- gather: out[d] = dinv[d] * (hs[d] + sum_{src} hs[src]) ----------
// One warp per node; slot ids preloaded into registers, src ids distributed
// via shfl -> all hs gathers independent (high MLP).
__global__ __launch_bounds__(256) void k_gather() {
    int warp = (blockIdx.x * 256 + threadIdx.x) >> 5;
    if (warp >= N_NODES) return;
    int lane = threadIdx.x & 31;
    int g = lane >> 2;        // edge group 0..7
    int f = lane & 3;         // float4 index 0..3

    int cnt = __ldg(&g_cnt[warp]);
    int m = cnt < CAP ? cnt : CAP;
    const int* slots = g_slots + warp * CAP;

    int s0 = 0, s1 = 0;
    if (lane < m)      s0 = __ldg(slots + lane);
    if (32 + lane < m) s1 = __ldg(slots + 32 + lane);

    float ax = 0.f, ay = 0.f, az = 0.f, aw = 0.f;
    int lim = m < 64 ? m : 64;
    #pragma unroll 2
    for (int e = 0; e < lim; e += 8) {
        int idx = e + g;
        int sv = (e < 32) ? __shfl_sync(0xFFFFFFFFu, s0, idx)
                          : __shfl_sync(0xFFFFFFFFu, s1, idx - 32);
        if (idx < lim) {
            float4 v = __ldg((const float4*)(g_hs + (long long)sv * HID) + f);
            ax += v.x; ay += v.y; az += v.z; aw += v.w;
        }
    }
    for (int e = 64; e < m; e += 8) {   // rare tail (deg > 64)
        int idx = e + g;
        if (idx < m) {
            int sv = __ldg(slots + idx);
            float4 v = __ldg((const float4*)(g_hs + (long long)sv * HID) + f);
            ax += v.x; ay += v.y; az += v.z; aw += v.w;
        }
    }

    #pragma unroll
    for (int off = 4; off < 32; off <<= 1) {
        ax += __shfl_xor_sync(0xFFFFFFFFu, ax, off);
        ay += __shfl_xor_sync(0xFFFFFFFFu, ay, off);
        az += __shfl_xor_sync(0xFFFFFFFFu, az, off);
        aw += __shfl_xor_sync(0xFFFFFFFFu, aw, off);
    }

    if (g == 0) {
        float4 self = __ldg((const float4*)(g_hs + (long long)warp * HID) + f);
        float dv = rsqrtf((float)(cnt + 1));
        float4 o = make_float4((ax + self.x) * dv, (ay + self.y) * dv,
                               (az + self.z) * dv, (aw + self.w) * dv);
        *((float4*)(g_out + (long long)warp * HID) + f) = o;
    }
}

// ---------- final: relu(out+bg) @ W2^T + b2 -> log_softmax ----------
__global__ __launch_bounds__(256) void k_final(
    const float* __restrict__ W2,
    const float* __restrict__ b2,
    const float* __restrict__ bg,
    float* __restrict__ out)
{
    __shared__ float sW2[N_CLASSES * HID];
    __shared__ float sb2[N_CLASSES];
    __shared__ float sbg[HID];
    int tid = threadIdx.x;
    for (int idx = tid; idx < N_CLASSES * HID; idx += 256) sW2[idx] = W2[idx];
    if (tid < N_CLASSES) sb2[tid] = b2[tid];
    if (tid < HID) sbg[tid] = bg[tid];
    __syncthreads();

    int i = blockIdx.x * 256 + tid;
    if (i >= N_NODES) return;

    float h[HID];
    const float4* a = (const float4*)(g_out + (long long)i * HID);
    #pragma unroll
    for (int q = 0; q < 4; q++) {
        float4 v = a[q];
        float v0 = v.x + sbg[4 * q + 0];
        float v1 = v.y + sbg[4 * q + 1];
        float v2 = v.z + sbg[4 * q + 2];
        float v3 = v.w + sbg[4 * q + 3];
        h[4 * q + 0] = v0 > 0.f ? v0 : 0.f;
        h[4 * q + 1] = v1 > 0.f ? v1 : 0.f;
        h[4 * q + 2] = v2 > 0.f ? v2 : 0.f;
        h[4 * q + 3] = v3 > 0.f ? v3 : 0.f;
    }

    float lg[N_CLASSES];
    float mx = -3.4e38f;
    #pragma unroll
    for (int c = 0; c < N_CLASSES; c++) {
        float s = sb2[c];
        #pragma unroll
        for (int j = 0; j < HID; j++) s += h[j] * sW2[c * HID + j];
        lg[c] = s;
        mx = fmaxf(mx, s);
    }
    float se = 0.f;
    #pragma unroll
    for (int c = 0; c < N_CLASSES; c++) se += __expf(lg[c] - mx);
    float lse = __logf(se) + mx;

    float* o = out + (long long)i * N_CLASSES;
    #pragma unroll
    for (int c4 = 0; c4 < N_CLASSES / 4; c4++) {
        ((float4*)o)[c4] = make_float4(lg[4 * c4 + 0] - lse, lg[4 * c4 + 1] - lse,
                                       lg[4 * c4 + 2] - lse, lg[4 * c4 + 3] - lse);
    }
}

extern "C" void kernel_launch(void* const* d_in, const int* in_sizes, int n_in,
                              void* d_out, int out_size) {
    const float* x  = (const float*)d_in[0];
    const void*  e  = d_in[1];
    const float* W1 = (const float*)d_in[2];
    const float* b1 = (const float*)d_in[3];
    const float* Wg = (const float*)d_in[4];
    const float* bg = (const float*)d_in[5];
    const float* W2 = (const float*)d_in[6];
    const float* b2 = (const float*)d_in[7];
    float* out = (float*)d_out;

    const int NB_N = (N_NODES + 255) / 256;
    const int NB_G = (N_NODES * 32 + 255) / 256;

    k_prep<<<NB_N, 256>>>(e);
    k_main<<<B_MAIN, 256>>>((const float4*)x, W1, b1, Wg, e);
    k_dinv<<<NB_N, 256>>>();
    k_gather<<<NB_G, 256>>>();
    k_final<<<NB_N, 256>>>(W2, b2, bg, out);
}